// round 6
// baseline (speedup 1.0000x reference)
#include <cuda_runtime.h>
#include <cuda_bf16.h>

// MedianPool2d 3x3, zero padding, x: [16, 3, 512, 512] fp32.
// v3: TX=4 x TY=16 tiles, single resident wave (6 CTAs/SM via launch_bounds),
// vertical rolling pair-min/max + shuffle halos. Exact median-of-9 via
// med3(max3(lo), med3(mid), min3(hi)).

#define MP_W 512
#define MP_H 512
#define MP_BC 48            // 16 * 3
#define MP_TX 4             // pixels per thread (horizontal)
#define MP_TY 16            // output rows per thread (vertical)
#define MP_SEGS 128         // MP_W / MP_TX
#define MP_BANDS 32         // MP_H / MP_TY
#define MP_NC (MP_TX + 2)   // 6 columns incl. halo

__device__ __forceinline__ float med3f(float a, float b, float c) {
    return fmaxf(fminf(a, b), fminf(fmaxf(a, b), c));
}

// Load row segment [xs-1, xs+4] into r[0..5]. Halos via lane shuffle;
// warp-edge lanes fall back to scalar LDG (or 0 at the image edge).
__device__ __forceinline__ void mp_load_row(const float* __restrict__ row,
                                            int xs, int lane, float r[MP_NC]) {
    float4 a = *(const float4*)(row + xs);
    r[1] = a.x; r[2] = a.y; r[3] = a.z; r[4] = a.w;
    float left  = __shfl_up_sync(0xffffffffu, a.w, 1);   // prev seg col 3
    float right = __shfl_down_sync(0xffffffffu, a.x, 1); // next seg col 0
    if (lane == 0)  left  = (xs > 0)            ? __ldg(row + xs - 1)     : 0.0f;
    if (lane == 31) right = (xs + MP_TX < MP_W) ? __ldg(row + xs + MP_TX) : 0.0f;
    r[0] = left; r[5] = right;
}

__global__ __launch_bounds__(256, 6)
void median3x3_v3(const float* __restrict__ in, float* __restrict__ out) {
    const int gid  = blockIdx.x * 256 + threadIdx.x;
    const int lane = threadIdx.x & 31;
    const int seg  = gid & (MP_SEGS - 1);          // bits [0,7)
    const int yb   = (gid >> 7) & (MP_BANDS - 1);  // bits [7,12)
    const int bc   = gid >> 12;                    // bits [12,...)
    const int xs   = seg * MP_TX;
    const int y0   = yb * MP_TY;

    const float* base = in + (size_t)bc * (MP_H * MP_W);
    const float* rptr = base + (size_t)y0 * MP_W;          // row y0
    float* optr = out + (size_t)bc * (MP_H * MP_W) + (size_t)y0 * MP_W + xs;

    // Rolling state: B = latest raw row; pm/px = pairwise min/max of the two
    // most recent raw rows (shared between consecutive vertical windows).
    float B[MP_NC], C[MP_NC], pm[MP_NC], px[MP_NC];

    if (y0 > 0) {
        float A[MP_NC];
        mp_load_row(rptr - MP_W, xs, lane, A);
        mp_load_row(rptr, xs, lane, B);
        #pragma unroll
        for (int i = 0; i < MP_NC; i++) {
            pm[i] = fminf(A[i], B[i]);
            px[i] = fmaxf(A[i], B[i]);
        }
    } else {
        mp_load_row(rptr, xs, lane, B);
        #pragma unroll
        for (int i = 0; i < MP_NC; i++) {
            pm[i] = fminf(0.0f, B[i]);
            px[i] = fmaxf(0.0f, B[i]);
        }
    }
    rptr += MP_W;  // points at row y0+1 (the next row to load)

    const bool last_band = (y0 + MP_TY >= MP_H);

    #pragma unroll
    for (int r = 0; r < MP_TY; r++) {
        if (r < MP_TY - 1 || !last_band) {
            mp_load_row(rptr, xs, lane, C);
        } else {
            #pragma unroll
            for (int i = 0; i < MP_NC; i++) C[i] = 0.0f;
        }
        rptr += MP_W;

        // sort3 of (prev2, prev1, C) via shared pair (pm, px):
        //   lo = min(pm,C); hi = max(px,C); mid = max(pm, min(px,C))
        // then advance pair to (B, C).
        float lo[MP_NC], mid[MP_NC], hi[MP_NC];
        #pragma unroll
        for (int i = 0; i < MP_NC; i++) {
            float t = fminf(px[i], C[i]);
            lo[i]  = fminf(pm[i], C[i]);
            hi[i]  = fmaxf(px[i], C[i]);
            mid[i] = fmaxf(pm[i], t);
            pm[i]  = fminf(B[i], C[i]);
            px[i]  = fmaxf(B[i], C[i]);
            B[i]   = C[i];
        }

        float o[MP_TX];
        #pragma unroll
        for (int i = 0; i < MP_TX; i++) {
            float mxlo = fmaxf(fmaxf(lo[i], lo[i + 1]), lo[i + 2]);
            float mnhi = fminf(fminf(hi[i], hi[i + 1]), hi[i + 2]);
            float mdmi = med3f(mid[i], mid[i + 1], mid[i + 2]);
            o[i] = med3f(mxlo, mdmi, mnhi);
        }

        *(float4*)optr = make_float4(o[0], o[1], o[2], o[3]);
        optr += MP_W;
    }
}

extern "C" void kernel_launch(void* const* d_in, const int* in_sizes, int n_in,
                              void* d_out, int out_size) {
    (void)in_sizes; (void)n_in; (void)out_size;
    const float* x = (const float*)d_in[0];
    float* out = (float*)d_out;
    const int total_threads = MP_BC * MP_BANDS * MP_SEGS;  // 196,608
    median3x3_v3<<<total_threads / 256, 256>>>(x, out);
}